// round 11
// baseline (speedup 1.0000x reference)
#include <cuda_runtime.h>
#include <cuda_fp16.h>
#include <cstdint>

// Problem constants
#define N_ROUTES  16384
#define ROUTE_LEN 32
#define D_GRAPH   512
#define D_ROUTE   1024
#define N_NODES   100000

// ---------------------------------------------------------------------------
// Device scratch (allocation-free).
// ---------------------------------------------------------------------------
__device__ __align__(256) __half g_ge16[(size_t)N_NODES * D_GRAPH];   // fp16 table
__device__ __align__(256) __half g_actA[(size_t)N_ROUTES * D_ROUTE];
__device__ __align__(256) __half g_actB[(size_t)N_ROUTES * D_ROUTE];
#define W0_OFF 0
#define W1_OFF (1024*512)
#define W2_OFF (1024*512 + 1024*1024)
#define W_ELEMS (1024*512 + 1024*1024 + 1024*1024)
__device__ __align__(256) __half g_w[W_ELEMS];

// ---------------------------------------------------------------------------
// Helpers
// ---------------------------------------------------------------------------
__device__ __forceinline__ uint32_t swz128(uint32_t b) { return b ^ ((b >> 3) & 0x70); }

__device__ __forceinline__ uint32_t smem_u32(const void* p) {
    uint32_t a;
    asm("{ .reg .u64 t; cvta.to.shared.u64 t, %1; cvt.u32.u64 %0, t; }" : "=r"(a) : "l"(p));
    return a;
}

__device__ __forceinline__ void cp16(uint32_t dst, const void* src) {
    asm volatile("cp.async.cg.shared.global [%0], [%1], 16;" :: "r"(dst), "l"(src) : "memory");
}
__device__ __forceinline__ void cp_commit() { asm volatile("cp.async.commit_group;" ::: "memory"); }
__device__ __forceinline__ void cp_wait0() { asm volatile("cp.async.wait_group 0;" ::: "memory"); }

__device__ __forceinline__ void ldsm_x4(uint32_t* r, uint32_t addr) {
    asm volatile("ldmatrix.sync.aligned.m8n8.x4.shared.b16 {%0,%1,%2,%3}, [%4];"
                 : "=r"(r[0]), "=r"(r[1]), "=r"(r[2]), "=r"(r[3]) : "r"(addr));
}

__device__ __forceinline__ void mma16816(float* d, const uint32_t* a, const uint32_t* b) {
    asm volatile(
        "mma.sync.aligned.m16n8k16.row.col.f32.f16.f16.f32 "
        "{%0,%1,%2,%3}, {%4,%5,%6,%7}, {%8,%9}, {%0,%1,%2,%3};"
        : "+f"(d[0]), "+f"(d[1]), "+f"(d[2]), "+f"(d[3])
        : "r"(a[0]), "r"(a[1]), "r"(a[2]), "r"(a[3]), "r"(b[0]), "r"(b[1]));
}

__device__ __forceinline__ uint4 hmax2x4(uint4 a, uint4 b) {
    __half2* pa = (__half2*)&a;
    __half2* pb = (__half2*)&b;
    uint4 r;
    __half2* pr = (__half2*)&r;
    pr[0] = __hmax2(pa[0], pb[0]);
    pr[1] = __hmax2(pa[1], pb[1]);
    pr[2] = __hmax2(pa[2], pb[2]);
    pr[3] = __hmax2(pa[3], pb[3]);
    return r;
}

// ---------------------------------------------------------------------------
// Table conversion: graph_embedding fp32 -> fp16 (leaves fp16 table hot in L2).
// ---------------------------------------------------------------------------
__global__ __launch_bounds__(256) void conv_kernel(
    const float* __restrict__ ge, __half* __restrict__ o)
{
    const size_t i = (size_t)blockIdx.x * 256 + threadIdx.x;   // 8 floats each
    const float4* p = (const float4*)ge;
    float4 a = p[2 * i];
    float4 b = p[2 * i + 1];
    __half2 h0 = __floats2half2_rn(a.x, a.y);
    __half2 h1 = __floats2half2_rn(a.z, a.w);
    __half2 h2 = __floats2half2_rn(b.x, b.y);
    __half2 h3 = __floats2half2_rn(b.z, b.w);
    uint4 u;
    u.x = *(uint32_t*)&h0; u.y = *(uint32_t*)&h1;
    u.z = *(uint32_t*)&h2; u.w = *(uint32_t*)&h3;
    ((uint4*)o)[i] = u;
}

// ---------------------------------------------------------------------------
// Gather + max on the fp16 table, per-route index-dtype self-detection.
// ---------------------------------------------------------------------------
__global__ __launch_bounds__(256) void gather_max_kernel(
    const __half* __restrict__ ge16,
    const unsigned int* __restrict__ w,
    __half* __restrict__ out)
{
    const int r = blockIdx.x;
    __shared__ int s_idx[ROUTE_LEN];
    __shared__ uint4 s_red[3][64];

    const int tid = threadIdx.x;
    if (tid < 32) {
        unsigned int odd = w[(size_t)r * 32 + 2 * (tid & 15) + 1];
        int is_i32 = __any_sync(0xFFFFFFFFu, (tid < 16) && odd != 0u);
        int v;
        if (is_i32) v = (int)w[(size_t)r * 32 + tid];
        else        v = (int)w[(size_t)r * 64 + 2 * tid];
        s_idx[tid] = v;
    }
    __syncthreads();

    const int g = tid & 63;
    const int q = tid >> 6;

    const uint4* row0 = (const uint4*)(ge16 + (size_t)s_idx[q * 8] * D_GRAPH);
    uint4 acc = __ldg(row0 + g);
    #pragma unroll 7
    for (int l = 1; l < 8; l++) {
        const uint4* row = (const uint4*)(ge16 + (size_t)s_idx[q * 8 + l] * D_GRAPH);
        acc = hmax2x4(acc, __ldg(row + g));
    }

    if (q) s_red[q - 1][g] = acc;
    __syncthreads();
    if (!q) {
        acc = hmax2x4(acc, s_red[0][g]);
        acc = hmax2x4(acc, s_red[1][g]);
        acc = hmax2x4(acc, s_red[2][g]);
        *(uint4*)(out + (size_t)r * D_GRAPH + g * 8) = acc;
    }
}

// ---------------------------------------------------------------------------
// Weight prep: W[K,N] fp32 -> transposed fp16 [N,K]
// ---------------------------------------------------------------------------
__global__ __launch_bounds__(256) void wconv_kernel(
    const float* __restrict__ W, int K, int N, __half* __restrict__ Wh)
{
    __shared__ float t[32][33];
    const int n0 = blockIdx.x * 32;
    const int k0 = blockIdx.y * 32;
    const int tx = threadIdx.x, ty = threadIdx.y;

    #pragma unroll
    for (int i = 0; i < 4; i++)
        t[ty + i * 8][tx] = W[(size_t)(k0 + ty + i * 8) * N + n0 + tx];
    __syncthreads();

    #pragma unroll
    for (int i = 0; i < 4; i++) {
        const int n = n0 + ty + i * 8;
        const int k = k0 + tx;
        Wh[(size_t)n * K + k] = __float2half_rn(t[tx][ty + i * 8]);
    }
}

// ---------------------------------------------------------------------------
// fp16 GEMM on mma.sync: C = relu(A @ B^T + bias)
// 128x128 CTA tile, 4 warps (2 M x 2 N), warp tile 64x64, m16n8k16.
// 2-stage buffer, 1-deep prefetch, single __syncthreads per chunk:
//   barrier at top of iter c proves all warps finished chunk c-1 (stage
//   (c-1)&1 == (c+1)&1 drained), then load(c+1) targets that freed stage
//   while compute(c) reads stage c&1. No aliasing.
// 64 KB smem/CTA -> 3 CTAs/SM = 12 warps/SM (3 per SMSP).
// Register layout: hold all 8 B fragments (16 regs), acc 128, transient A 4.
// ---------------------------------------------------------------------------
#define STAGE_BYTES 32768
#define T_A 0
#define T_B 16384

__device__ __forceinline__ void load_chunk(
    uint32_t sbase, int c, int tid, int m0, int n0, int K,
    const __half* A, const __half* B)
{
    const int r0  = tid >> 3;      // 0..15
    const int seg = tid & 7;
    const uint32_t st = sbase + (uint32_t)(c & 1) * STAGE_BYTES;
    const size_t koff = (size_t)c * 64 + seg * 8;
    #pragma unroll
    for (int i = 0; i < 8; i++) {
        const int row = r0 + i * 16;
        const uint32_t sw = swz128((uint32_t)(row * 128 + seg * 16));
        cp16(st + T_A + sw, A + (size_t)(m0 + row) * K + koff);
        cp16(st + T_B + sw, B + (size_t)(n0 + row) * K + koff);
    }
    cp_commit();
}

__global__ __launch_bounds__(128, 3) void gemm_fp16(
    int K, int nchunks,
    const __half* __restrict__ A, const __half* __restrict__ B,
    const float* __restrict__ bias,
    float* __restrict__ Cf, __half* __restrict__ Ch)
{
    extern __shared__ __align__(1024) char smem[];
    __shared__ float s_bias[128];

    const int tid  = threadIdx.x;
    const int wid  = tid >> 5;
    const int lane = tid & 31;
    const int m0 = blockIdx.y * 128;
    const int n0 = blockIdx.x * 128;
    const int wm = (wid >> 1) * 64;   // 0/64
    const int wn = (wid & 1) * 64;    // 0/64

    const uint32_t sbase = smem_u32(smem);
    s_bias[tid] = bias[n0 + tid];

    // 1-deep prefetch over a 2-stage buffer
    load_chunk(sbase, 0, tid, m0, n0, K, A, B);

    float acc[4][8][4];
    #pragma unroll
    for (int i = 0; i < 4; i++)
        #pragma unroll
        for (int j = 0; j < 8; j++)
            #pragma unroll
            for (int q = 0; q < 4; q++) acc[i][j][q] = 0.0f;

    for (int c = 0; c < nchunks; c++) {
        cp_wait0();        // chunk c landed
        __syncthreads();   // all warps done with chunk c-1 -> stage (c+1)&1 free

        if (c + 1 < nchunks)
            load_chunk(sbase, c + 1, tid, m0, n0, K, A, B);   // overlaps compute(c)

        const uint32_t st = sbase + (uint32_t)(c & 1) * STAGE_BYTES;

        #pragma unroll
        for (int ks = 0; ks < 4; ks++) {
            const uint32_t kb = ks * 32;

            // All 8 B n-tiles: 4 x ldsm_x4 (held across the mt loop)
            uint32_t bf[8][2];
            #pragma unroll
            for (int ntp = 0; ntp < 4; ntp++) {
                const uint32_t off = swz128(
                    (uint32_t)((wn + ntp * 16 + ((lane >> 4) & 1) * 8 + (lane & 7)) * 128)
                    + kb + ((lane >> 3) & 1) * 16);
                uint32_t r[4];
                ldsm_x4(r, st + T_B + off);
                bf[ntp * 2 + 0][0] = r[0]; bf[ntp * 2 + 0][1] = r[1];
                bf[ntp * 2 + 1][0] = r[2]; bf[ntp * 2 + 1][1] = r[3];
            }

            #pragma unroll
            for (int mt = 0; mt < 4; mt++) {
                const uint32_t aoff = swz128(
                    (uint32_t)((wm + mt * 16 + (lane & 15)) * 128) + kb + ((lane >> 4) & 1) * 16);
                uint32_t af[4];
                ldsm_x4(af, st + T_A + aoff);
                #pragma unroll
                for (int nt = 0; nt < 8; nt++)
                    mma16816(acc[mt][nt], af, bf[nt]);
            }
        }
    }

    // Epilogue
    const int rbase = m0 + wm + (lane >> 2);
    const int cloc0 = wn + (lane & 3) * 2;
    #pragma unroll
    for (int mt = 0; mt < 4; mt++) {
        #pragma unroll
        for (int half = 0; half < 2; half++) {
            const int row = rbase + mt * 16 + half * 8;
            #pragma unroll
            for (int nt = 0; nt < 8; nt++) {
                const int cl = cloc0 + nt * 8;
                float v0 = fmaxf(acc[mt][nt][half * 2 + 0] + s_bias[cl + 0], 0.0f);
                float v1 = fmaxf(acc[mt][nt][half * 2 + 1] + s_bias[cl + 1], 0.0f);
                const size_t off = (size_t)row * D_ROUTE + n0 + cl;
                if (Cf) {
                    *(float2*)(Cf + off) = make_float2(v0, v1);
                } else {
                    __half2 hp = __halves2half2(__float2half_rn(v0), __float2half_rn(v1));
                    *(uint32_t*)(Ch + off) = *(uint32_t*)&hp;
                }
            }
        }
    }
}

// ---------------------------------------------------------------------------
// kernel_launch
// Inputs: graph_embedding, locations_idx, W0, b0, W1, b1, W2, b2
// ---------------------------------------------------------------------------
extern "C" void kernel_launch(void* const* d_in, const int* in_sizes, int n_in,
                              void* d_out, int out_size)
{
    const float* ge  = (const float*)d_in[0];
    const void*  idx = d_in[1];
    const float* W0  = (const float*)d_in[2];
    const float* b0  = (const float*)d_in[3];
    const float* W1  = (const float*)d_in[4];
    const float* b1  = (const float*)d_in[5];
    const float* W2  = (const float*)d_in[6];
    const float* b2  = (const float*)d_in[7];
    float* out = (float*)d_out;

    __half *ge16, *actA, *actB, *w;
    cudaGetSymbolAddress((void**)&ge16, g_ge16);
    cudaGetSymbolAddress((void**)&actA, g_actA);
    cudaGetSymbolAddress((void**)&actB, g_actB);
    cudaGetSymbolAddress((void**)&w,    g_w);

    const int smem_bytes = 2 * STAGE_BYTES;   // 64 KB -> 3 CTAs/SM
    cudaFuncSetAttribute(gemm_fp16, cudaFuncAttributeMaxDynamicSharedMemorySize, smem_bytes);

    // 1. fp32 -> fp16 table
    conv_kernel<<<25000, 256>>>(ge, ge16);

    // 2. gather + max (self-detecting index dtype) -> fp16 activations
    gather_max_kernel<<<N_ROUTES, 256>>>(ge16, (const unsigned int*)idx, actA);

    // 3-5. weight prep
    dim3 blk(32, 8);
    wconv_kernel<<<dim3(1024 / 32, 512 / 32),  blk>>>(W0, 512,  1024, w + W0_OFF);
    wconv_kernel<<<dim3(1024 / 32, 1024 / 32), blk>>>(W1, 1024, 1024, w + W1_OFF);
    wconv_kernel<<<dim3(1024 / 32, 1024 / 32), blk>>>(W2, 1024, 1024, w + W2_OFF);

    // 6-8. three GEMM layers
    dim3 grid(D_ROUTE / 128, N_ROUTES / 128);   // (8, 128) = 1024 CTAs
    gemm_fp16<<<grid, 128, smem_bytes>>>(512,  8,  actA, w + W0_OFF, b0, nullptr, actB);
    gemm_fp16<<<grid, 128, smem_bytes>>>(1024, 16, actB, w + W1_OFF, b1, nullptr, actA);
    gemm_fp16<<<grid, 128, smem_bytes>>>(1024, 16, actA, w + W2_OFF, b2, out, nullptr);
}

// round 12
// speedup vs baseline: 1.1777x; 1.1777x over previous
#include <cuda_runtime.h>
#include <cuda_fp16.h>
#include <cstdint>

// Problem constants
#define N_ROUTES  16384
#define ROUTE_LEN 32
#define D_GRAPH   512
#define D_ROUTE   1024
#define N_NODES   100000

// ---------------------------------------------------------------------------
// Device scratch (allocation-free).
// ---------------------------------------------------------------------------
__device__ __align__(256) __half g_ge16[(size_t)N_NODES * D_GRAPH];   // fp16 table
__device__ __align__(256) __half g_actA[(size_t)N_ROUTES * D_ROUTE];
__device__ __align__(256) __half g_actB[(size_t)N_ROUTES * D_ROUTE];
#define W0_OFF 0
#define W1_OFF (1024*512)
#define W2_OFF (1024*512 + 1024*1024)
#define W_ELEMS (1024*512 + 1024*1024 + 1024*1024)
__device__ __align__(256) __half g_w[W_ELEMS];

// ---------------------------------------------------------------------------
// Helpers
// ---------------------------------------------------------------------------
__device__ __forceinline__ uint32_t swz128(uint32_t b) { return b ^ ((b >> 3) & 0x70); }

__device__ __forceinline__ uint32_t smem_u32(const void* p) {
    uint32_t a;
    asm("{ .reg .u64 t; cvta.to.shared.u64 t, %1; cvt.u32.u64 %0, t; }" : "=r"(a) : "l"(p));
    return a;
}

__device__ __forceinline__ void cp16(uint32_t dst, const void* src) {
    asm volatile("cp.async.cg.shared.global [%0], [%1], 16;" :: "r"(dst), "l"(src) : "memory");
}
__device__ __forceinline__ void cp_commit() { asm volatile("cp.async.commit_group;" ::: "memory"); }
__device__ __forceinline__ void cp_wait1() { asm volatile("cp.async.wait_group 1;" ::: "memory"); }

__device__ __forceinline__ void ldsm_x4(uint32_t* r, uint32_t addr) {
    asm volatile("ldmatrix.sync.aligned.m8n8.x4.shared.b16 {%0,%1,%2,%3}, [%4];"
                 : "=r"(r[0]), "=r"(r[1]), "=r"(r[2]), "=r"(r[3]) : "r"(addr));
}

__device__ __forceinline__ void mma16816(float* d, const uint32_t* a, const uint32_t* b) {
    asm volatile(
        "mma.sync.aligned.m16n8k16.row.col.f32.f16.f16.f32 "
        "{%0,%1,%2,%3}, {%4,%5,%6,%7}, {%8,%9}, {%0,%1,%2,%3};"
        : "+f"(d[0]), "+f"(d[1]), "+f"(d[2]), "+f"(d[3])
        : "r"(a[0]), "r"(a[1]), "r"(a[2]), "r"(a[3]), "r"(b[0]), "r"(b[1]));
}

__device__ __forceinline__ uint4 hmax2x4(uint4 a, uint4 b) {
    __half2* pa = (__half2*)&a;
    __half2* pb = (__half2*)&b;
    uint4 r;
    __half2* pr = (__half2*)&r;
    pr[0] = __hmax2(pa[0], pb[0]);
    pr[1] = __hmax2(pa[1], pb[1]);
    pr[2] = __hmax2(pa[2], pb[2]);
    pr[3] = __hmax2(pa[3], pb[3]);
    return r;
}

// ---------------------------------------------------------------------------
// Table conversion: graph_embedding fp32 -> fp16 (leaves fp16 table hot in L2).
// ---------------------------------------------------------------------------
__global__ __launch_bounds__(256) void conv_kernel(
    const float* __restrict__ ge, __half* __restrict__ o)
{
    const size_t i = (size_t)blockIdx.x * 256 + threadIdx.x;   // 8 floats each
    const float4* p = (const float4*)ge;
    float4 a = p[2 * i];
    float4 b = p[2 * i + 1];
    __half2 h0 = __floats2half2_rn(a.x, a.y);
    __half2 h1 = __floats2half2_rn(a.z, a.w);
    __half2 h2 = __floats2half2_rn(b.x, b.y);
    __half2 h3 = __floats2half2_rn(b.z, b.w);
    uint4 u;
    u.x = *(uint32_t*)&h0; u.y = *(uint32_t*)&h1;
    u.z = *(uint32_t*)&h2; u.w = *(uint32_t*)&h3;
    ((uint4*)o)[i] = u;
}

// ---------------------------------------------------------------------------
// Gather + max on the fp16 table, per-route index-dtype self-detection.
// ---------------------------------------------------------------------------
__global__ __launch_bounds__(256) void gather_max_kernel(
    const __half* __restrict__ ge16,
    const unsigned int* __restrict__ w,
    __half* __restrict__ out)
{
    const int r = blockIdx.x;
    __shared__ int s_idx[ROUTE_LEN];
    __shared__ uint4 s_red[3][64];

    const int tid = threadIdx.x;
    if (tid < 32) {
        unsigned int odd = w[(size_t)r * 32 + 2 * (tid & 15) + 1];
        int is_i32 = __any_sync(0xFFFFFFFFu, (tid < 16) && odd != 0u);
        int v;
        if (is_i32) v = (int)w[(size_t)r * 32 + tid];
        else        v = (int)w[(size_t)r * 64 + 2 * tid];
        s_idx[tid] = v;
    }
    __syncthreads();

    const int g = tid & 63;
    const int q = tid >> 6;

    const uint4* row0 = (const uint4*)(ge16 + (size_t)s_idx[q * 8] * D_GRAPH);
    uint4 acc = __ldg(row0 + g);
    #pragma unroll 7
    for (int l = 1; l < 8; l++) {
        const uint4* row = (const uint4*)(ge16 + (size_t)s_idx[q * 8 + l] * D_GRAPH);
        acc = hmax2x4(acc, __ldg(row + g));
    }

    if (q) s_red[q - 1][g] = acc;
    __syncthreads();
    if (!q) {
        acc = hmax2x4(acc, s_red[0][g]);
        acc = hmax2x4(acc, s_red[1][g]);
        acc = hmax2x4(acc, s_red[2][g]);
        *(uint4*)(out + (size_t)r * D_GRAPH + g * 8) = acc;
    }
}

// ---------------------------------------------------------------------------
// Weight prep: W[K,N] fp32 -> transposed fp16 [N,K]
// ---------------------------------------------------------------------------
__global__ __launch_bounds__(256) void wconv_kernel(
    const float* __restrict__ W, int K, int N, __half* __restrict__ Wh)
{
    __shared__ float t[32][33];
    const int n0 = blockIdx.x * 32;
    const int k0 = blockIdx.y * 32;
    const int tx = threadIdx.x, ty = threadIdx.y;

    #pragma unroll
    for (int i = 0; i < 4; i++)
        t[ty + i * 8][tx] = W[(size_t)(k0 + ty + i * 8) * N + n0 + tx];
    __syncthreads();

    #pragma unroll
    for (int i = 0; i < 4; i++) {
        const int n = n0 + ty + i * 8;
        const int k = k0 + tx;
        Wh[(size_t)n * K + k] = __float2half_rn(t[tx][ty + i * 8]);
    }
}

// ---------------------------------------------------------------------------
// fp16 GEMM on mma.sync: C = relu(A @ B^T + bias)   [R10 config, proven]
// 128x128 CTA tile, 8 warps (2 M x 4 N), warp tile 64x32, m16n8k16.
// 3-stage buffer, 2-deep cp.async pipeline (32 KB/stage = 96 KB -> 2 CTAs/SM),
// single __syncthreads per chunk. Tail load issued BEFORE compute (safety
// identical: barrier proved stage (c-1)%3 == (c+2)%3 drained; strictly more
// overlap than issuing after compute).
// ---------------------------------------------------------------------------
#define STAGE_BYTES 32768
#define T_A 0
#define T_B 16384

__device__ __forceinline__ void load_chunk(
    uint32_t sbase, int c, int tid, int m0, int n0, int K,
    const __half* A, const __half* B)
{
    const int r0  = tid >> 3;      // 0..31
    const int seg = tid & 7;
    const uint32_t st = sbase + (uint32_t)(c % 3) * STAGE_BYTES;
    const size_t koff = (size_t)c * 64 + seg * 8;
    #pragma unroll
    for (int i = 0; i < 4; i++) {
        const int row = r0 + i * 32;
        const uint32_t sw = swz128((uint32_t)(row * 128 + seg * 16));
        cp16(st + T_A + sw, A + (size_t)(m0 + row) * K + koff);
        cp16(st + T_B + sw, B + (size_t)(n0 + row) * K + koff);
    }
    cp_commit();
}

__global__ __launch_bounds__(256, 2) void gemm_fp16(
    int K, int nchunks,
    const __half* __restrict__ A, const __half* __restrict__ B,
    const float* __restrict__ bias,
    float* __restrict__ Cf, __half* __restrict__ Ch)
{
    extern __shared__ __align__(1024) char smem[];
    __shared__ float s_bias[128];

    const int tid  = threadIdx.x;
    const int wid  = tid >> 5;
    const int lane = tid & 31;
    const int m0 = blockIdx.y * 128;
    const int n0 = blockIdx.x * 128;
    const int wm = (wid >> 2) * 64;   // 0/64
    const int wn = (wid & 3) * 32;    // 0/32/64/96

    const uint32_t sbase = smem_u32(smem);
    if (tid < 128) s_bias[tid] = bias[n0 + tid];

    // Preload 2 chunks (2-deep pipeline over a 3-stage buffer)
    load_chunk(sbase, 0, tid, m0, n0, K, A, B);
    load_chunk(sbase, 1, tid, m0, n0, K, A, B);

    float acc[4][4][4];
    #pragma unroll
    for (int i = 0; i < 4; i++)
        #pragma unroll
        for (int j = 0; j < 4; j++)
            #pragma unroll
            for (int q = 0; q < 4; q++) acc[i][j][q] = 0.0f;

    for (int c = 0; c < nchunks; c++) {
        cp_wait1();        // chunk c's loads complete (≤1 group pending)
        __syncthreads();   // all warps done with chunk c-1 -> stage (c-1)%3 free

        // Early tail load into stage (c+2)%3 == (c-1)%3 (drained per barrier);
        // overlaps the entire compute body below.
        if (c + 2 < nchunks)
            load_chunk(sbase, c + 2, tid, m0, n0, K, A, B);

        const uint32_t st = sbase + (uint32_t)(c % 3) * STAGE_BYTES;

        #pragma unroll
        for (int ks = 0; ks < 4; ks++) {
            const uint32_t kb = ks * 32;

            // B fragments: 2 x ldsm_x4, each covering two adjacent n-tiles
            uint32_t bf[4][2];
            #pragma unroll
            for (int ntp = 0; ntp < 2; ntp++) {
                const uint32_t off = swz128(
                    (uint32_t)((wn + ntp * 16 + ((lane >> 4) & 1) * 8 + (lane & 7)) * 128)
                    + kb + ((lane >> 3) & 1) * 16);
                uint32_t r[4];
                ldsm_x4(r, st + T_B + off);
                bf[ntp * 2 + 0][0] = r[0]; bf[ntp * 2 + 0][1] = r[1];
                bf[ntp * 2 + 1][0] = r[2]; bf[ntp * 2 + 1][1] = r[3];
            }

            #pragma unroll
            for (int mt = 0; mt < 4; mt++) {
                const uint32_t aoff = swz128(
                    (uint32_t)((wm + mt * 16 + (lane & 15)) * 128) + kb + ((lane >> 4) & 1) * 16);
                uint32_t af[4];
                ldsm_x4(af, st + T_A + aoff);
                #pragma unroll
                for (int nt = 0; nt < 4; nt++)
                    mma16816(acc[mt][nt], af, bf[nt]);
            }
        }
    }

    // Epilogue
    const int rbase = m0 + wm + (lane >> 2);
    const int cloc0 = wn + (lane & 3) * 2;
    #pragma unroll
    for (int mt = 0; mt < 4; mt++) {
        #pragma unroll
        for (int half = 0; half < 2; half++) {
            const int row = rbase + mt * 16 + half * 8;
            #pragma unroll
            for (int nt = 0; nt < 4; nt++) {
                const int cl = cloc0 + nt * 8;
                float v0 = fmaxf(acc[mt][nt][half * 2 + 0] + s_bias[cl + 0], 0.0f);
                float v1 = fmaxf(acc[mt][nt][half * 2 + 1] + s_bias[cl + 1], 0.0f);
                const size_t off = (size_t)row * D_ROUTE + n0 + cl;
                if (Cf) {
                    *(float2*)(Cf + off) = make_float2(v0, v1);
                } else {
                    __half2 hp = __halves2half2(__float2half_rn(v0), __float2half_rn(v1));
                    *(uint32_t*)(Ch + off) = *(uint32_t*)&hp;
                }
            }
        }
    }
}

// ---------------------------------------------------------------------------
// kernel_launch
// Inputs: graph_embedding, locations_idx, W0, b0, W1, b1, W2, b2
// ---------------------------------------------------------------------------
extern "C" void kernel_launch(void* const* d_in, const int* in_sizes, int n_in,
                              void* d_out, int out_size)
{
    const float* ge  = (const float*)d_in[0];
    const void*  idx = d_in[1];
    const float* W0  = (const float*)d_in[2];
    const float* b0  = (const float*)d_in[3];
    const float* W1  = (const float*)d_in[4];
    const float* b1  = (const float*)d_in[5];
    const float* W2  = (const float*)d_in[6];
    const float* b2  = (const float*)d_in[7];
    float* out = (float*)d_out;

    __half *ge16, *actA, *actB, *w;
    cudaGetSymbolAddress((void**)&ge16, g_ge16);
    cudaGetSymbolAddress((void**)&actA, g_actA);
    cudaGetSymbolAddress((void**)&actB, g_actB);
    cudaGetSymbolAddress((void**)&w,    g_w);

    const int smem_bytes = 3 * STAGE_BYTES;   // 96 KB -> 2 CTAs/SM
    cudaFuncSetAttribute(gemm_fp16, cudaFuncAttributeMaxDynamicSharedMemorySize, smem_bytes);

    // 1. fp32 -> fp16 table
    conv_kernel<<<25000, 256>>>(ge, ge16);

    // 2. gather + max (self-detecting index dtype) -> fp16 activations
    gather_max_kernel<<<N_ROUTES, 256>>>(ge16, (const unsigned int*)idx, actA);

    // 3-5. weight prep
    dim3 blk(32, 8);
    wconv_kernel<<<dim3(1024 / 32, 512 / 32),  blk>>>(W0, 512,  1024, w + W0_OFF);
    wconv_kernel<<<dim3(1024 / 32, 1024 / 32), blk>>>(W1, 1024, 1024, w + W1_OFF);
    wconv_kernel<<<dim3(1024 / 32, 1024 / 32), blk>>>(W2, 1024, 1024, w + W2_OFF);

    // 6-8. three GEMM layers
    dim3 grid(D_ROUTE / 128, N_ROUTES / 128);   // (8, 128) = 1024 CTAs
    gemm_fp16<<<grid, 256, smem_bytes>>>(512,  8,  actA, w + W0_OFF, b0, nullptr, actB);
    gemm_fp16<<<grid, 256, smem_bytes>>>(1024, 16, actB, w + W1_OFF, b1, nullptr, actA);
    gemm_fp16<<<grid, 256, smem_bytes>>>(1024, 16, actA, w + W2_OFF, b2, out, nullptr);
}

// round 13
// speedup vs baseline: 1.2155x; 1.0321x over previous
#include <cuda_runtime.h>
#include <cuda_fp16.h>
#include <cstdint>

// Problem constants
#define N_ROUTES  16384
#define ROUTE_LEN 32
#define D_GRAPH   512
#define D_ROUTE   1024
#define N_NODES   100000

// ---------------------------------------------------------------------------
// Device scratch (allocation-free).
// ---------------------------------------------------------------------------
__device__ __align__(256) __half g_ge16[(size_t)N_NODES * D_GRAPH];   // fp16 table
__device__ __align__(256) __half g_actA[(size_t)N_ROUTES * D_ROUTE];
__device__ __align__(256) __half g_actB[(size_t)N_ROUTES * D_ROUTE];
#define W0_OFF 0
#define W1_OFF (1024*512)
#define W2_OFF (1024*512 + 1024*1024)
#define W_ELEMS (1024*512 + 1024*1024 + 1024*1024)
__device__ __align__(256) __half g_w[W_ELEMS];

// ---------------------------------------------------------------------------
// Helpers
// ---------------------------------------------------------------------------
__device__ __forceinline__ uint32_t swz128(uint32_t b) { return b ^ ((b >> 3) & 0x70); }

__device__ __forceinline__ uint32_t smem_u32(const void* p) {
    uint32_t a;
    asm("{ .reg .u64 t; cvta.to.shared.u64 t, %1; cvt.u32.u64 %0, t; }" : "=r"(a) : "l"(p));
    return a;
}

__device__ __forceinline__ void cp16(uint32_t dst, const void* src) {
    asm volatile("cp.async.cg.shared.global [%0], [%1], 16;" :: "r"(dst), "l"(src) : "memory");
}
__device__ __forceinline__ void cp_commit() { asm volatile("cp.async.commit_group;" ::: "memory"); }
__device__ __forceinline__ void cp_wait1() { asm volatile("cp.async.wait_group 1;" ::: "memory"); }

__device__ __forceinline__ void ldsm_x4(uint32_t* r, uint32_t addr) {
    asm volatile("ldmatrix.sync.aligned.m8n8.x4.shared.b16 {%0,%1,%2,%3}, [%4];"
                 : "=r"(r[0]), "=r"(r[1]), "=r"(r[2]), "=r"(r[3]) : "r"(addr));
}

__device__ __forceinline__ void mma16816(float* d, const uint32_t* a, const uint32_t* b) {
    asm volatile(
        "mma.sync.aligned.m16n8k16.row.col.f32.f16.f16.f32 "
        "{%0,%1,%2,%3}, {%4,%5,%6,%7}, {%8,%9}, {%0,%1,%2,%3};"
        : "+f"(d[0]), "+f"(d[1]), "+f"(d[2]), "+f"(d[3])
        : "r"(a[0]), "r"(a[1]), "r"(a[2]), "r"(a[3]), "r"(b[0]), "r"(b[1]));
}

__device__ __forceinline__ uint4 hmax2x4(uint4 a, uint4 b) {
    __half2* pa = (__half2*)&a;
    __half2* pb = (__half2*)&b;
    uint4 r;
    __half2* pr = (__half2*)&r;
    pr[0] = __hmax2(pa[0], pb[0]);
    pr[1] = __hmax2(pa[1], pb[1]);
    pr[2] = __hmax2(pa[2], pb[2]);
    pr[3] = __hmax2(pa[3], pb[3]);
    return r;
}

// ---------------------------------------------------------------------------
// Table conversion: graph_embedding fp32 -> fp16 (leaves fp16 table hot in L2).
// ---------------------------------------------------------------------------
__global__ __launch_bounds__(256) void conv_kernel(
    const float* __restrict__ ge, __half* __restrict__ o)
{
    const size_t i = (size_t)blockIdx.x * 256 + threadIdx.x;   // 8 floats each
    const float4* p = (const float4*)ge;
    float4 a = p[2 * i];
    float4 b = p[2 * i + 1];
    __half2 h0 = __floats2half2_rn(a.x, a.y);
    __half2 h1 = __floats2half2_rn(a.z, a.w);
    __half2 h2 = __floats2half2_rn(b.x, b.y);
    __half2 h3 = __floats2half2_rn(b.z, b.w);
    uint4 u;
    u.x = *(uint32_t*)&h0; u.y = *(uint32_t*)&h1;
    u.z = *(uint32_t*)&h2; u.w = *(uint32_t*)&h3;
    ((uint4*)o)[i] = u;
}

// ---------------------------------------------------------------------------
// Gather + max on the fp16 table, per-route index-dtype self-detection.
// ---------------------------------------------------------------------------
__global__ __launch_bounds__(256) void gather_max_kernel(
    const __half* __restrict__ ge16,
    const unsigned int* __restrict__ w,
    __half* __restrict__ out)
{
    const int r = blockIdx.x;
    __shared__ int s_idx[ROUTE_LEN];
    __shared__ uint4 s_red[3][64];

    const int tid = threadIdx.x;
    if (tid < 32) {
        unsigned int odd = w[(size_t)r * 32 + 2 * (tid & 15) + 1];
        int is_i32 = __any_sync(0xFFFFFFFFu, (tid < 16) && odd != 0u);
        int v;
        if (is_i32) v = (int)w[(size_t)r * 32 + tid];
        else        v = (int)w[(size_t)r * 64 + 2 * tid];
        s_idx[tid] = v;
    }
    __syncthreads();

    const int g = tid & 63;
    const int q = tid >> 6;

    const uint4* row0 = (const uint4*)(ge16 + (size_t)s_idx[q * 8] * D_GRAPH);
    uint4 acc = __ldg(row0 + g);
    #pragma unroll 7
    for (int l = 1; l < 8; l++) {
        const uint4* row = (const uint4*)(ge16 + (size_t)s_idx[q * 8 + l] * D_GRAPH);
        acc = hmax2x4(acc, __ldg(row + g));
    }

    if (q) s_red[q - 1][g] = acc;
    __syncthreads();
    if (!q) {
        acc = hmax2x4(acc, s_red[0][g]);
        acc = hmax2x4(acc, s_red[1][g]);
        acc = hmax2x4(acc, s_red[2][g]);
        *(uint4*)(out + (size_t)r * D_GRAPH + g * 8) = acc;
    }
}

// ---------------------------------------------------------------------------
// Fused weight prep: all three W[K,N] fp32 -> transposed fp16 [N,K].
// grid = (32, 32, 3); z selects layer; z=0 uses only y<16 (K=512).
// ---------------------------------------------------------------------------
__global__ __launch_bounds__(256) void wconv_all_kernel(
    const float* __restrict__ W0, const float* __restrict__ W1,
    const float* __restrict__ W2, __half* __restrict__ w)
{
    const int z = blockIdx.z;
    const float* W;
    __half* Wh;
    int K;
    if (z == 0)      { W = W0; Wh = w + W0_OFF; K = 512; }
    else if (z == 1) { W = W1; Wh = w + W1_OFF; K = 1024; }
    else             { W = W2; Wh = w + W2_OFF; K = 1024; }

    const int k0 = blockIdx.y * 32;
    if (k0 >= K) return;
    const int n0 = blockIdx.x * 32;
    const int N = 1024;
    const int tx = threadIdx.x, ty = threadIdx.y;

    __shared__ float t[32][33];
    #pragma unroll
    for (int i = 0; i < 4; i++)
        t[ty + i * 8][tx] = W[(size_t)(k0 + ty + i * 8) * N + n0 + tx];
    __syncthreads();

    #pragma unroll
    for (int i = 0; i < 4; i++) {
        const int n = n0 + ty + i * 8;
        const int k = k0 + tx;
        Wh[(size_t)n * K + k] = __float2half_rn(t[tx][ty + i * 8]);
    }
}

// ---------------------------------------------------------------------------
// fp16 GEMM on mma.sync: C = relu(A @ B^T + bias)   [R10 config — proven 325.8]
// 128x128 CTA tile, 8 warps (2 M x 4 N), warp tile 64x32, m16n8k16.
// 3-stage buffer, 2-deep cp.async pipeline (32 KB/stage = 96 KB -> 2 CTAs/SM),
// single __syncthreads per chunk, tail load AFTER compute (R12 showed the
// early-issue variant adds MIO contention at the ldmatrix burst).
// ---------------------------------------------------------------------------
#define STAGE_BYTES 32768
#define T_A 0
#define T_B 16384

__device__ __forceinline__ void load_chunk(
    uint32_t sbase, int c, int tid, int m0, int n0, int K,
    const __half* A, const __half* B)
{
    const int r0  = tid >> 3;      // 0..31
    const int seg = tid & 7;
    const uint32_t st = sbase + (uint32_t)(c % 3) * STAGE_BYTES;
    const size_t koff = (size_t)c * 64 + seg * 8;
    #pragma unroll
    for (int i = 0; i < 4; i++) {
        const int row = r0 + i * 32;
        const uint32_t sw = swz128((uint32_t)(row * 128 + seg * 16));
        cp16(st + T_A + sw, A + (size_t)(m0 + row) * K + koff);
        cp16(st + T_B + sw, B + (size_t)(n0 + row) * K + koff);
    }
    cp_commit();
}

__global__ __launch_bounds__(256, 2) void gemm_fp16(
    int K, int nchunks,
    const __half* __restrict__ A, const __half* __restrict__ B,
    const float* __restrict__ bias,
    float* __restrict__ Cf, __half* __restrict__ Ch)
{
    extern __shared__ __align__(1024) char smem[];
    __shared__ float s_bias[128];

    const int tid  = threadIdx.x;
    const int wid  = tid >> 5;
    const int lane = tid & 31;
    const int m0 = blockIdx.y * 128;
    const int n0 = blockIdx.x * 128;
    const int wm = (wid >> 2) * 64;   // 0/64
    const int wn = (wid & 3) * 32;    // 0/32/64/96

    const uint32_t sbase = smem_u32(smem);
    if (tid < 128) s_bias[tid] = bias[n0 + tid];

    // Preload 2 chunks (2-deep pipeline over a 3-stage buffer)
    load_chunk(sbase, 0, tid, m0, n0, K, A, B);
    load_chunk(sbase, 1, tid, m0, n0, K, A, B);

    float acc[4][4][4];
    #pragma unroll
    for (int i = 0; i < 4; i++)
        #pragma unroll
        for (int j = 0; j < 4; j++)
            #pragma unroll
            for (int q = 0; q < 4; q++) acc[i][j][q] = 0.0f;

    for (int c = 0; c < nchunks; c++) {
        cp_wait1();        // chunk c's loads complete (≤1 group pending)
        __syncthreads();   // all warps done with chunk c-1 -> stage (c-1)%3 free

        const uint32_t st = sbase + (uint32_t)(c % 3) * STAGE_BYTES;

        #pragma unroll
        for (int ks = 0; ks < 4; ks++) {
            const uint32_t kb = ks * 32;

            // B fragments: 2 x ldsm_x4, each covering two adjacent n-tiles
            uint32_t bf[4][2];
            #pragma unroll
            for (int ntp = 0; ntp < 2; ntp++) {
                const uint32_t off = swz128(
                    (uint32_t)((wn + ntp * 16 + ((lane >> 4) & 1) * 8 + (lane & 7)) * 128)
                    + kb + ((lane >> 3) & 1) * 16);
                uint32_t r[4];
                ldsm_x4(r, st + T_B + off);
                bf[ntp * 2 + 0][0] = r[0]; bf[ntp * 2 + 0][1] = r[1];
                bf[ntp * 2 + 1][0] = r[2]; bf[ntp * 2 + 1][1] = r[3];
            }

            #pragma unroll
            for (int mt = 0; mt < 4; mt++) {
                const uint32_t aoff = swz128(
                    (uint32_t)((wm + mt * 16 + (lane & 15)) * 128) + kb + ((lane >> 4) & 1) * 16);
                uint32_t af[4];
                ldsm_x4(af, st + T_A + aoff);
                #pragma unroll
                for (int nt = 0; nt < 4; nt++)
                    mma16816(acc[mt][nt], af, bf[nt]);
            }
        }

        // Tail load into stage (c+2)%3 == (c-1)%3 (drained per top barrier)
        if (c + 2 < nchunks)
            load_chunk(sbase, c + 2, tid, m0, n0, K, A, B);
    }

    // Epilogue
    const int rbase = m0 + wm + (lane >> 2);
    const int cloc0 = wn + (lane & 3) * 2;
    #pragma unroll
    for (int mt = 0; mt < 4; mt++) {
        #pragma unroll
        for (int half = 0; half < 2; half++) {
            const int row = rbase + mt * 16 + half * 8;
            #pragma unroll
            for (int nt = 0; nt < 4; nt++) {
                const int cl = cloc0 + nt * 8;
                float v0 = fmaxf(acc[mt][nt][half * 2 + 0] + s_bias[cl + 0], 0.0f);
                float v1 = fmaxf(acc[mt][nt][half * 2 + 1] + s_bias[cl + 1], 0.0f);
                const size_t off = (size_t)row * D_ROUTE + n0 + cl;
                if (Cf) {
                    *(float2*)(Cf + off) = make_float2(v0, v1);
                } else {
                    __half2 hp = __halves2half2(__float2half_rn(v0), __float2half_rn(v1));
                    *(uint32_t*)(Ch + off) = *(uint32_t*)&hp;
                }
            }
        }
    }
}

// ---------------------------------------------------------------------------
// kernel_launch
// Inputs: graph_embedding, locations_idx, W0, b0, W1, b1, W2, b2
// ---------------------------------------------------------------------------
extern "C" void kernel_launch(void* const* d_in, const int* in_sizes, int n_in,
                              void* d_out, int out_size)
{
    const float* ge  = (const float*)d_in[0];
    const void*  idx = d_in[1];
    const float* W0  = (const float*)d_in[2];
    const float* b0  = (const float*)d_in[3];
    const float* W1  = (const float*)d_in[4];
    const float* b1  = (const float*)d_in[5];
    const float* W2  = (const float*)d_in[6];
    const float* b2  = (const float*)d_in[7];
    float* out = (float*)d_out;

    __half *ge16, *actA, *actB, *w;
    cudaGetSymbolAddress((void**)&ge16, g_ge16);
    cudaGetSymbolAddress((void**)&actA, g_actA);
    cudaGetSymbolAddress((void**)&actB, g_actB);
    cudaGetSymbolAddress((void**)&w,    g_w);

    const int smem_bytes = 3 * STAGE_BYTES;   // 96 KB -> 2 CTAs/SM
    cudaFuncSetAttribute(gemm_fp16, cudaFuncAttributeMaxDynamicSharedMemorySize, smem_bytes);

    // 1. fp32 -> fp16 table
    conv_kernel<<<25000, 256>>>(ge, ge16);

    // 2. gather + max (self-detecting index dtype) -> fp16 activations
    gather_max_kernel<<<N_ROUTES, 256>>>(ge16, (const unsigned int*)idx, actA);

    // 3. fused weight prep (one launch for all three layers)
    wconv_all_kernel<<<dim3(32, 32, 3), dim3(32, 8)>>>(W0, W1, W2, w);

    // 4-6. three GEMM layers
    dim3 grid(D_ROUTE / 128, N_ROUTES / 128);   // (8, 128) = 1024 CTAs
    gemm_fp16<<<grid, 256, smem_bytes>>>(512,  8,  actA, w + W0_OFF, b0, nullptr, actB);
    gemm_fp16<<<grid, 256, smem_bytes>>>(1024, 16, actB, w + W1_OFF, b1, nullptr, actA);
    gemm_fp16<<<grid, 256, smem_bytes>>>(1024, 16, actA, w + W2_OFF, b2, out, nullptr);
}